// round 11
// baseline (speedup 1.0000x reference)
#include <cuda_runtime.h>
#include <cuda_bf16.h>
#include <cstdint>

#define B_  2
#define L_  2048
#define V_  1024
#define H_  16
#define HD_ 64
#define EPS_ 1e-3f
#define BLV_ (B_*L_*V_)      // 4194304
#define NV_  (V_*V_)         // 1048576
#define LOG2E_ 1.44269504088896f

// fp32 scratch (attention output for LN)
__device__ float g_Hd[BLV_];

// bf16 split operands for projections (inputs)
__device__ __nv_bfloat16 g_Xhi[3*BLV_];
__device__ __nv_bfloat16 g_Xlo[3*BLV_];
__device__ __nv_bfloat16 g_Wthi[3*NV_];   // [p][n=h*64+d][v]
__device__ __nv_bfloat16 g_Wtlo[3*NV_];

// bf16 split projection OUTPUTS: p=0 Q(*0.125*log2e), p=1 K, p=2 V(*vmask)
__device__ __nv_bfloat16 g_Ah[3*BLV_];
__device__ __nv_bfloat16 g_Al[3*BLV_];

// ---------------------------------------------------------------------------
// helpers
// ---------------------------------------------------------------------------
__device__ __forceinline__ uint32_t smem_u32(const void* p) {
    uint32_t a;
    asm("{ .reg .u64 t; cvta.to.shared.u64 t, %1; cvt.u32.u64 %0, t; }" : "=r"(a) : "l"(p));
    return a;
}
__device__ __forceinline__ void ldsm4(uint32_t* r, uint32_t addr) {
    asm volatile("ldmatrix.sync.aligned.m8n8.x4.shared.b16 {%0,%1,%2,%3}, [%4];"
        : "=r"(r[0]), "=r"(r[1]), "=r"(r[2]), "=r"(r[3]) : "r"(addr));
}
__device__ __forceinline__ void ldsm4t(uint32_t* r, uint32_t addr) {
    asm volatile("ldmatrix.sync.aligned.m8n8.x4.trans.shared.b16 {%0,%1,%2,%3}, [%4];"
        : "=r"(r[0]), "=r"(r[1]), "=r"(r[2]), "=r"(r[3]) : "r"(addr));
}
__device__ __forceinline__ void mma16816(float* c, const uint32_t* a, const uint32_t* b) {
    asm volatile("mma.sync.aligned.m16n8k16.row.col.f32.bf16.bf16.f32 "
        "{%0,%1,%2,%3}, {%4,%5,%6,%7}, {%8,%9}, {%0,%1,%2,%3};"
        : "+f"(c[0]), "+f"(c[1]), "+f"(c[2]), "+f"(c[3])
        : "r"(a[0]), "r"(a[1]), "r"(a[2]), "r"(a[3]), "r"(b[0]), "r"(b[1]));
}
__device__ __forceinline__ void cp16(uint32_t dst, const void* src) {
    asm volatile("cp.async.cg.shared.global [%0], [%1], 16;" :: "r"(dst), "l"(src));
}
__device__ __forceinline__ float fexp2(float x) {
    float y;
    asm("ex2.approx.f32 %0, %1;" : "=f"(y) : "f"(x));
    return y;
}
__device__ __forceinline__ uint32_t pack_hi2(float x, float y, float& rx, float& ry) {
    __nv_bfloat16 hx = __float2bfloat16_rn(x);
    __nv_bfloat16 hy = __float2bfloat16_rn(y);
    rx = x - __bfloat162float(hx);
    ry = y - __bfloat162float(hy);
    return ((uint32_t)__bfloat16_as_ushort(hy) << 16) | (uint32_t)__bfloat16_as_ushort(hx);
}
__device__ __forceinline__ uint32_t pack_bf2(float x, float y) {
    return ((uint32_t)__bfloat16_as_ushort(__float2bfloat16_rn(y)) << 16)
         | (uint32_t)__bfloat16_as_ushort(__float2bfloat16_rn(x));
}

// ---------------------------------------------------------------------------
// Convert X (q, key_t, value) -> bf16 hi/lo
// ---------------------------------------------------------------------------
__global__ __launch_bounds__(256) void convx_kernel(
    const float* __restrict__ q, const float* __restrict__ kt, const float* __restrict__ v)
{
    int p = blockIdx.y;
    const float* X = (p == 0) ? q : (p == 1) ? kt : v;
    __nv_bfloat16* hi = g_Xhi + (size_t)p * BLV_;
    __nv_bfloat16* lo = g_Xlo + (size_t)p * BLV_;
    size_t i0 = ((size_t)blockIdx.x * 256 + threadIdx.x) * 8;
    float x[8];
    *(float4*)&x[0] = *(const float4*)(X + i0);
    *(float4*)&x[4] = *(const float4*)(X + i0 + 4);
    __nv_bfloat16 hb[8], lb[8];
    #pragma unroll
    for (int i = 0; i < 8; i++) {
        __nv_bfloat16 h = __float2bfloat16_rn(x[i]);
        hb[i] = h;
        lb[i] = __float2bfloat16_rn(x[i] - __bfloat162float(h));
    }
    *(uint4*)(hi + i0) = *(uint4*)hb;
    *(uint4*)(lo + i0) = *(uint4*)lb;
}

// ---------------------------------------------------------------------------
// Convert + transpose W: W[h][v][d] -> Wt[n=h*64+d][v] bf16 hi/lo
// ---------------------------------------------------------------------------
__global__ __launch_bounds__(256) void convw_kernel(
    const float* __restrict__ Wq, const float* __restrict__ Wk, const float* __restrict__ Wv)
{
    __shared__ float s[64][65];
    int v0 = blockIdx.x * 64, h = blockIdx.y, p = blockIdx.z;
    const float* W = ((p == 0) ? Wq : (p == 1) ? Wk : Wv) + (size_t)h * V_ * HD_;
    __nv_bfloat16* Whi = g_Wthi + (size_t)p * NV_;
    __nv_bfloat16* Wlo = g_Wtlo + (size_t)p * NV_;
    int t = threadIdx.x;
    int r16 = t >> 4, c4 = (t & 15) * 4;
    #pragma unroll
    for (int u = 0; u < 4; u++) {
        int row = r16 + u * 16;
        float4 a = *(const float4*)(W + (size_t)(v0 + row) * HD_ + c4);
        s[row][c4 + 0] = a.x; s[row][c4 + 1] = a.y; s[row][c4 + 2] = a.z; s[row][c4 + 3] = a.w;
    }
    __syncthreads();
    #pragma unroll
    for (int u = 0; u < 4; u++) {
        int d = r16 + u * 16;
        __nv_bfloat16 hb[4], lb[4];
        #pragma unroll
        for (int j = 0; j < 4; j++) {
            float x = s[c4 + j][d];
            __nv_bfloat16 hh = __float2bfloat16_rn(x);
            hb[j] = hh;
            lb[j] = __float2bfloat16_rn(x - __bfloat162float(hh));
        }
        size_t o = ((size_t)(h * 64 + d) << 10) + v0 + c4;
        *(uint2*)(Whi + o) = *(uint2*)hb;
        *(uint2*)(Wlo + o) = *(uint2*)lb;
    }
}

// ---------------------------------------------------------------------------
// Projection GEMM via mma.sync bf16 3-term split, 2-stage cp.async pipeline.
// Writes bf16 hi/lo directly: p=0 Q*0.125*log2e, p=1 K, p=2 V*vmask.
// ---------------------------------------------------------------------------
#define SK_ 40
#define PMAT_ (128 * SK_ * 2)      // one matrix tile bytes: 10240
#define PSTG_ (4 * PMAT_)          // one stage: 40960
#define PROJ_SMEM (2 * PSTG_)      // 81920

__global__ __launch_bounds__(256) void proj_mma_kernel(const int* __restrict__ vmask)
{
    extern __shared__ __nv_bfloat16 psm[];
    uint32_t smb = smem_u32(psm);

    int tid = threadIdx.x;
    int wid = tid >> 5, lane = tid & 31;
    int warp_m = wid & 3, warp_n = wid >> 2;

    int l0  = blockIdx.x * 128;
    int n0g = blockIdx.y * 128;
    int p   = blockIdx.z >> 1;
    int b   = blockIdx.z & 1;

    const __nv_bfloat16* Xhi = g_Xhi + (size_t)p * BLV_ + (size_t)b * L_ * V_;
    const __nv_bfloat16* Xlo = g_Xlo + (size_t)p * BLV_ + (size_t)b * L_ * V_;
    const __nv_bfloat16* Whi = g_Wthi + (size_t)p * NV_;
    const __nv_bfloat16* Wlo = g_Wtlo + (size_t)p * NV_;
    __nv_bfloat16* Ah = g_Ah + (size_t)p * BLV_ + (size_t)b * L_ * V_;
    __nv_bfloat16* Al = g_Al + (size_t)p * BLV_ + (size_t)b * L_ * V_;

    float acc[2][8][4] = {};

    int ld_row = tid >> 2;          // 0..63 (plus +64 via u)
    int ld_c8  = (tid & 3) * 8;

    uint32_t a_row = (uint32_t)(warp_m * 32 + (lane & 15));
    uint32_t a_koff = (uint32_t)((lane >> 4) * 8);
    uint32_t b_row = (uint32_t)(warp_n * 64 + ((lane >> 4) & 1) * 8 + (lane & 7));
    uint32_t b_koff = (uint32_t)(((lane >> 3) & 1) * 8);

    // prefetch chunk kc into stage st
    auto prefetch = [&](int kc, int st) {
        int k0 = kc * 32;
        uint32_t base = smb + st * PSTG_;
        #pragma unroll
        for (int u = 0; u < 2; u++) {
            int row = ld_row + u * 64;
            uint32_t so = (uint32_t)(row * SK_ + ld_c8) * 2;
            size_t goA = ((size_t)(l0 + row) << 10) + k0 + ld_c8;
            size_t goB = ((size_t)(n0g + row) << 10) + k0 + ld_c8;
            cp16(base + 0 * PMAT_ + so, Xhi + goA);
            cp16(base + 1 * PMAT_ + so, Xlo + goA);
            cp16(base + 2 * PMAT_ + so, Whi + goB);
            cp16(base + 3 * PMAT_ + so, Wlo + goB);
        }
        asm volatile("cp.async.commit_group;" ::: "memory");
    };

    prefetch(0, 0);

    for (int kc = 0; kc < V_ / 32; kc++) {
        if (kc + 1 < V_ / 32) {
            prefetch(kc + 1, (kc + 1) & 1);
            asm volatile("cp.async.wait_group 1;" ::: "memory");
        } else {
            asm volatile("cp.async.wait_group 0;" ::: "memory");
        }
        __syncthreads();

        uint32_t base = smb + (kc & 1) * PSTG_;
        #pragma unroll
        for (int ks = 0; ks < 2; ks++) {
            uint32_t ah[2][4], al[2][4];
            #pragma unroll
            for (int mt = 0; mt < 2; mt++) {
                uint32_t off = ((a_row + mt * 16) * SK_ + ks * 16 + a_koff) * 2;
                ldsm4(ah[mt], base + 0 * PMAT_ + off);
                ldsm4(al[mt], base + 1 * PMAT_ + off);
            }
            uint32_t bh[4][4], bl[4][4];
            #pragma unroll
            for (int nt2 = 0; nt2 < 4; nt2++) {
                uint32_t off = ((b_row + nt2 * 16) * SK_ + ks * 16 + b_koff) * 2;
                ldsm4(bh[nt2], base + 2 * PMAT_ + off);
                ldsm4(bl[nt2], base + 3 * PMAT_ + off);
            }
            #pragma unroll
            for (int mt = 0; mt < 2; mt++)
                #pragma unroll
                for (int nt = 0; nt < 8; nt++) {
                    const uint32_t* bfh = &bh[nt >> 1][(nt & 1) * 2];
                    const uint32_t* bfl = &bl[nt >> 1][(nt & 1) * 2];
                    mma16816(acc[mt][nt], ah[mt], bfh);
                    mma16816(acc[mt][nt], ah[mt], bfl);
                    mma16816(acc[mt][nt], al[mt], bfh);
                }
        }
        __syncthreads();
    }

    // Epilogue: scale + split hi/lo + 4B stores
    int mrow = warp_m * 32 + (lane >> 2);
    int ncol = warp_n * 64 + 2 * (lane & 3);
    #pragma unroll
    for (int mt = 0; mt < 2; mt++) {
        int m0r = l0 + mrow + mt * 16;
        float s0 = 1.f, s1 = 1.f;
        if (p == 0) { s0 = 0.125f * LOG2E_; s1 = s0; }
        else if (p == 2) {
            s0 = (float)vmask[b * L_ + m0r];
            s1 = (float)vmask[b * L_ + m0r + 8];
        }
        #pragma unroll
        for (int nt = 0; nt < 8; nt++) {
            int n = ncol + nt * 8;
            float r0, r1;
            uint32_t hi0 = pack_hi2(acc[mt][nt][0] * s0, acc[mt][nt][1] * s0, r0, r1);
            uint32_t lo0 = pack_bf2(r0, r1);
            *(uint32_t*)(Ah + (size_t)m0r * V_ + n0g + n) = hi0;
            *(uint32_t*)(Al + (size_t)m0r * V_ + n0g + n) = lo0;
            uint32_t hi1 = pack_hi2(acc[mt][nt][2] * s1, acc[mt][nt][3] * s1, r0, r1);
            uint32_t lo1 = pack_bf2(r0, r1);
            *(uint32_t*)(Ah + (size_t)(m0r + 8) * V_ + n0g + n) = hi1;
            *(uint32_t*)(Al + (size_t)(m0r + 8) * V_ + n0g + n) = lo1;
        }
    }
}

// ---------------------------------------------------------------------------
// Tensor-core flash attention; scores arrive in log2 domain (Q pre-scaled by
// 0.125*log2e), softmax via ex2.approx. Full-row denominator; post-softmax
// causal mask on numerator; vmask folded into V; qmask in epilogue.
// ---------------------------------------------------------------------------
#define SKA_ 72
#define QH_OFF 0
#define QL_OFF (128 * SKA_)
#define BUF0_  (2 * 128 * SKA_)
#define KHO_   0
#define KLO_   (64 * SKA_)
#define VHO_   (2 * 64 * SKA_)
#define VLO_   (3 * 64 * SKA_)
#define BUFS_  (4 * 64 * SKA_)
#define ATT_SMEM ((BUF0_ + 2 * BUFS_) * 2)   // 110592 bytes

__global__ __launch_bounds__(256, 2) void attn_mma_kernel(const int* __restrict__ qmask)
{
    extern __shared__ __nv_bfloat16 smb16[];
    uint32_t smb = smem_u32(smb16);

    int b  = blockIdx.z, h = blockIdx.y;
    int l0 = blockIdx.x * 128;
    int tid = threadIdx.x;
    int w = tid >> 5, lane = tid & 31;

    const __nv_bfloat16* Qh = g_Ah + ((size_t)b * L_) * V_ + h * HD_;
    const __nv_bfloat16* Ql = g_Al + ((size_t)b * L_) * V_ + h * HD_;
    const __nv_bfloat16* Kh = g_Ah + (size_t)1 * BLV_ + ((size_t)b * L_) * V_ + h * HD_;
    const __nv_bfloat16* Kl = g_Al + (size_t)1 * BLV_ + ((size_t)b * L_) * V_ + h * HD_;
    const __nv_bfloat16* Vh = g_Ah + (size_t)2 * BLV_ + ((size_t)b * L_) * V_ + h * HD_;
    const __nv_bfloat16* Vl = g_Al + (size_t)2 * BLV_ + ((size_t)b * L_) * V_ + h * HD_;

    const int kt_pv = 2 * blockIdx.x + 1;

    // ---- Load Q tile (128x64 hi/lo) ----
    #pragma unroll
    for (int u = 0; u < 4; u++) {
        int idx = tid + u * 256;
        int row = idx >> 3, ch = (idx & 7) * 8;
        *(uint4*)(smb16 + QH_OFF + row * SKA_ + ch) = *(const uint4*)(Qh + (size_t)(l0 + row) * V_ + ch);
        *(uint4*)(smb16 + QL_OFF + row * SKA_ + ch) = *(const uint4*)(Ql + (size_t)(l0 + row) * V_ + ch);
    }

    int pf_row0 = tid >> 3, pf_ch = (tid & 7) * 8;

    // ---- Prefetch tile 0 ----
    {
        uint32_t base = smb + BUF0_ * 2;
        #pragma unroll
        for (int u = 0; u < 2; u++) {
            int row = pf_row0 + u * 32;
            uint32_t so = (uint32_t)(row * SKA_ + pf_ch) * 2;
            size_t go = (size_t)row * V_ + pf_ch;
            cp16(base + KHO_ * 2 + so, Kh + go);
            cp16(base + KLO_ * 2 + so, Kl + go);
            cp16(base + VHO_ * 2 + so, Vh + go);
            cp16(base + VLO_ * 2 + so, Vl + go);
        }
        asm volatile("cp.async.commit_group;" ::: "memory");
    }

    uint32_t qa_row  = (uint32_t)(w * 16 + (lane & 15));
    uint32_t qa_koff = (uint32_t)((lane >> 4) * 8);
    uint32_t kb_row  = (uint32_t)(((lane >> 4) & 1) * 8 + (lane & 7));
    uint32_t kb_koff = (uint32_t)(((lane >> 3) & 1) * 8);
    uint32_t vb_row  = (uint32_t)(((lane >> 3) & 1) * 8 + (lane & 7));
    uint32_t vb_coff = (uint32_t)((lane >> 4) * 8);

    float o[8][4] = {};
    float rmax0 = -1e30f, rmax1 = -1e30f;
    float rden0 = 0.f, rden1 = 0.f;

    for (int kt = 0; kt < L_ / 64; kt++) {
        int m0 = kt * 64;
        bool need_pv = (kt <= kt_pv);

        if (kt < L_ / 64 - 1) {
            int m1 = m0 + 64;
            bool pv1 = (kt + 1 <= kt_pv);
            uint32_t base = smb + (BUF0_ + ((kt + 1) & 1) * BUFS_) * 2;
            #pragma unroll
            for (int u = 0; u < 2; u++) {
                int row = pf_row0 + u * 32;
                uint32_t so = (uint32_t)(row * SKA_ + pf_ch) * 2;
                size_t go = (size_t)(m1 + row) * V_ + pf_ch;
                cp16(base + KHO_ * 2 + so, Kh + go);
                cp16(base + KLO_ * 2 + so, Kl + go);
                if (pv1) {
                    cp16(base + VHO_ * 2 + so, Vh + go);
                    cp16(base + VLO_ * 2 + so, Vl + go);
                }
            }
            asm volatile("cp.async.commit_group;" ::: "memory");
            asm volatile("cp.async.wait_group 1;" ::: "memory");
        } else {
            asm volatile("cp.async.wait_group 0;" ::: "memory");
        }
        __syncthreads();

        uint32_t kbase = smb + (BUF0_ + (kt & 1) * BUFS_) * 2;

        // ---- S' = (Q*0.125*log2e) K^T, 3-term split ----
        float s[8][4] = {};
        #pragma unroll
        for (int ks = 0; ks < 4; ks++) {
            uint32_t ah[4], al[4];
            uint32_t qoff = (qa_row * SKA_ + ks * 16 + qa_koff) * 2;
            ldsm4(ah, smb + QH_OFF * 2 + qoff);
            ldsm4(al, smb + QL_OFF * 2 + qoff);
            #pragma unroll
            for (int nt = 0; nt < 4; nt++) {
                uint32_t bh[4], bl[4];
                uint32_t koff = ((nt * 16 + kb_row) * SKA_ + ks * 16 + kb_koff) * 2;
                ldsm4(bh, kbase + KHO_ * 2 + koff);
                ldsm4(bl, kbase + KLO_ * 2 + koff);
                #pragma unroll
                for (int half = 0; half < 2; half++) {
                    float* sj = s[2 * nt + half];
                    mma16816(sj, ah, &bh[half * 2]);
                    mma16816(sj, ah, &bl[half * 2]);
                    mma16816(sj, al, &bh[half * 2]);
                }
            }
        }

        // ---- Online softmax in log2 domain (full row; 2 rows per thread) ----
        float ml0 = -1e30f, ml1 = -1e30f;
        #pragma unroll
        for (int j = 0; j < 8; j++) {
            ml0 = fmaxf(ml0, fmaxf(s[j][0], s[j][1]));
            ml1 = fmaxf(ml1, fmaxf(s[j][2], s[j][3]));
        }
        ml0 = fmaxf(ml0, __shfl_xor_sync(0xffffffffu, ml0, 1));
        ml0 = fmaxf(ml0, __shfl_xor_sync(0xffffffffu, ml0, 2));
        ml1 = fmaxf(ml1, __shfl_xor_sync(0xffffffffu, ml1, 1));
        ml1 = fmaxf(ml1, __shfl_xor_sync(0xffffffffu, ml1, 2));

        float mn0 = fmaxf(rmax0, ml0), mn1 = fmaxf(rmax1, ml1);
        float sc0 = fexp2(rmax0 - mn0), sc1 = fexp2(rmax1 - mn1);
        rmax0 = mn0; rmax1 = mn1;

        float rs0 = 0.f, rs1 = 0.f;
        #pragma unroll
        for (int j = 0; j < 8; j++) {
            s[j][0] = fexp2(s[j][0] - mn0);
            s[j][1] = fexp2(s[j][1] - mn0);
            s[j][2] = fexp2(s[j][2] - mn1);
            s[j][3] = fexp2(s[j][3] - mn1);
            rs0 += s[j][0] + s[j][1];
            rs1 += s[j][2] + s[j][3];
        }
        rs0 += __shfl_xor_sync(0xffffffffu, rs0, 1);
        rs0 += __shfl_xor_sync(0xffffffffu, rs0, 2);
        rs1 += __shfl_xor_sync(0xffffffffu, rs1, 1);
        rs1 += __shfl_xor_sync(0xffffffffu, rs1, 2);
        rden0 = rden0 * sc0 + rs0;
        rden1 = rden1 * sc1 + rs1;
        #pragma unroll
        for (int j = 0; j < 8; j++) {
            o[j][0] *= sc0; o[j][1] *= sc0;
            o[j][2] *= sc1; o[j][3] *= sc1;
        }

        if (need_pv) {
            int lg0 = l0 + w * 16 + (lane >> 2);
            int lg1 = lg0 + 8;
            #pragma unroll
            for (int j = 0; j < 8; j++) {
                int mg = m0 + (j >> 1) * 16 + (j & 1) * 8 + (lane & 3) * 2;
                if (mg > lg0)     s[j][0] = 0.f;
                if (mg + 1 > lg0) s[j][1] = 0.f;
                if (mg > lg1)     s[j][2] = 0.f;
                if (mg + 1 > lg1) s[j][3] = 0.f;
            }
            #pragma unroll
            for (int kc = 0; kc < 4; kc++) {
                int j0 = 2 * kc, j1 = 2 * kc + 1;
                uint32_t ap[4], alo[4];
                float r0, r1;
                ap[0] = pack_hi2(s[j0][0], s[j0][1], r0, r1); alo[0] = pack_bf2(r0, r1);
                ap[1] = pack_hi2(s[j0][2], s[j0][3], r0, r1); alo[1] = pack_bf2(r0, r1);
                ap[2] = pack_hi2(s[j1][0], s[j1][1], r0, r1); alo[2] = pack_bf2(r0, r1);
                ap[3] = pack_hi2(s[j1][2], s[j1][3], r0, r1); alo[3] = pack_bf2(r0, r1);
                #pragma unroll
                for (int nt = 0; nt < 4; nt++) {
                    uint32_t bvh[4], bvl[4];
                    uint32_t voff = ((kc * 16 + vb_row) * SKA_ + nt * 16 + vb_coff) * 2;
                    ldsm4t(bvh, kbase + VHO_ * 2 + voff);
                    ldsm4t(bvl, kbase + VLO_ * 2 + voff);
                    #pragma unroll
                    for (int half = 0; half < 2; half++) {
                        float* oj = o[2 * nt + half];
                        mma16816(oj, ap, &bvh[half * 2]);
                        mma16816(oj, ap, &bvl[half * 2]);
                        mma16816(oj, alo, &bvh[half * 2]);
                    }
                }
            }
        }
        __syncthreads();
    }

    // ---- Epilogue: qm / den, write heads ----
    int lg0 = l0 + w * 16 + (lane >> 2);
    int lg1 = lg0 + 8;
    float inv0 = (float)qmask[b * L_ + lg0] / rden0;
    float inv1 = (float)qmask[b * L_ + lg1] / rden1;
    float* Og = g_Hd + ((size_t)b * L_) * V_ + h * HD_;
    #pragma unroll
    for (int j = 0; j < 8; j++) {
        int d = (j >> 1) * 16 + (j & 1) * 8 + (lane & 3) * 2;
        float2 a0 = {o[j][0] * inv0, o[j][1] * inv0};
        float2 a1 = {o[j][2] * inv1, o[j][3] * inv1};
        *(float2*)(Og + (size_t)lg0 * V_ + d) = a0;
        *(float2*)(Og + (size_t)lg1 * V_ + d) = a1;
    }
}

// ---------------------------------------------------------------------------
// Residual + LayerNorm
// ---------------------------------------------------------------------------
__global__ __launch_bounds__(256) void ln_kernel(
    const float* __restrict__ query, const float* __restrict__ gamma,
    const float* __restrict__ beta, float* __restrict__ out)
{
    __shared__ float rsum[8], rsum2[8], stats[2];
    int row = blockIdx.x, tid = threadIdx.x;
    const float* hrow = g_Hd + (size_t)row * V_;
    const float* qrow = query + (size_t)row * V_;

    float4 h4 = *(const float4*)(hrow + tid * 4);
    float4 q4 = *(const float4*)(qrow + tid * 4);
    float y[4] = {h4.x + q4.x, h4.y + q4.y, h4.z + q4.z, h4.w + q4.w};
    float s  = y[0] + y[1] + y[2] + y[3];
    float s2 = y[0]*y[0] + y[1]*y[1] + y[2]*y[2] + y[3]*y[3];
    #pragma unroll
    for (int off = 16; off; off >>= 1) {
        s  += __shfl_xor_sync(0xffffffffu, s,  off);
        s2 += __shfl_xor_sync(0xffffffffu, s2, off);
    }
    if ((tid & 31) == 0) { rsum[tid >> 5] = s; rsum2[tid >> 5] = s2; }
    __syncthreads();
    if (tid == 0) {
        float ts = 0.f, ts2 = 0.f;
        #pragma unroll
        for (int i = 0; i < 8; i++) { ts += rsum[i]; ts2 += rsum2[i]; }
        float mu  = ts * (1.f / V_);
        float var = ts2 * (1.f / V_) - mu * mu;
        stats[0] = mu;
        stats[1] = rsqrtf(var + EPS_);
    }
    __syncthreads();
    float mu = stats[0], inv = stats[1];
    float4 g4 = *(const float4*)(gamma + tid * 4);
    float4 b4 = *(const float4*)(beta  + tid * 4);
    float4 o;
    o.x = g4.x * (y[0] - mu) * inv + b4.x;
    o.y = g4.y * (y[1] - mu) * inv + b4.y;
    o.z = g4.z * (y[2] - mu) * inv + b4.z;
    o.w = g4.w * (y[3] - mu) * inv + b4.w;
    *(float4*)(out + (size_t)row * V_ + tid * 4) = o;
}

// ---------------------------------------------------------------------------
extern "C" void kernel_launch(void* const* d_in, const int* in_sizes, int n_in,
                              void* d_out, int out_size)
{
    const float* query = (const float*)d_in[0];
    const float* key_t = (const float*)d_in[1];
    const float* value = (const float*)d_in[2];
    const float* Wq    = (const float*)d_in[3];
    const float* Wk    = (const float*)d_in[4];
    const float* Wv    = (const float*)d_in[5];
    const float* gamma = (const float*)d_in[6];
    const float* beta  = (const float*)d_in[7];
    const int*   qmask = (const int*)d_in[8];
    const int*   vmask = (const int*)d_in[9];
    float* out = (float*)d_out;

    convx_kernel<<<dim3(BLV_ / 2048, 3), 256>>>(query, key_t, value);
    convw_kernel<<<dim3(V_ / 64, H_, 3), 256>>>(Wq, Wk, Wv);

    cudaFuncSetAttribute(proj_mma_kernel, cudaFuncAttributeMaxDynamicSharedMemorySize, PROJ_SMEM);
    proj_mma_kernel<<<dim3(L_ / 128, V_ / 128, 3 * B_), 256, PROJ_SMEM>>>(vmask);

    cudaFuncSetAttribute(attn_mma_kernel, cudaFuncAttributeMaxDynamicSharedMemorySize, ATT_SMEM);
    attn_mma_kernel<<<dim3(L_ / 128, H_, B_), 256, ATT_SMEM>>>(qmask);

    ln_kernel<<<B_ * L_, 256>>>(query, gamma, beta, out);
}

// round 12
// speedup vs baseline: 1.1131x; 1.1131x over previous
#include <cuda_runtime.h>
#include <cuda_bf16.h>
#include <cstdint>

#define B_  2
#define L_  2048
#define V_  1024
#define H_  16
#define HD_ 64
#define EPS_ 1e-3f
#define BLV_ (B_*L_*V_)      // 4194304
#define NV_  (V_*V_)         // 1048576
#define LOG2E_ 1.44269504088896f

// fp32 scratch (attention output for LN)
__device__ float g_Hd[BLV_];

// bf16 split operands for projections (inputs)
__device__ __nv_bfloat16 g_Xhi[3*BLV_];
__device__ __nv_bfloat16 g_Xlo[3*BLV_];
__device__ __nv_bfloat16 g_Wthi[3*NV_];   // [p][n=h*64+d][v]
__device__ __nv_bfloat16 g_Wtlo[3*NV_];

// bf16 split projection OUTPUTS: p=0 Q(*0.125*log2e), p=1 K, p=2 V(*vmask)
__device__ __nv_bfloat16 g_Ah[3*BLV_];
__device__ __nv_bfloat16 g_Al[3*BLV_];

// ---------------------------------------------------------------------------
// helpers
// ---------------------------------------------------------------------------
__device__ __forceinline__ uint32_t smem_u32(const void* p) {
    uint32_t a;
    asm("{ .reg .u64 t; cvta.to.shared.u64 t, %1; cvt.u32.u64 %0, t; }" : "=r"(a) : "l"(p));
    return a;
}
__device__ __forceinline__ void ldsm4(uint32_t* r, uint32_t addr) {
    asm volatile("ldmatrix.sync.aligned.m8n8.x4.shared.b16 {%0,%1,%2,%3}, [%4];"
        : "=r"(r[0]), "=r"(r[1]), "=r"(r[2]), "=r"(r[3]) : "r"(addr));
}
__device__ __forceinline__ void ldsm4t(uint32_t* r, uint32_t addr) {
    asm volatile("ldmatrix.sync.aligned.m8n8.x4.trans.shared.b16 {%0,%1,%2,%3}, [%4];"
        : "=r"(r[0]), "=r"(r[1]), "=r"(r[2]), "=r"(r[3]) : "r"(addr));
}
__device__ __forceinline__ void mma16816(float* c, const uint32_t* a, const uint32_t* b) {
    asm volatile("mma.sync.aligned.m16n8k16.row.col.f32.bf16.bf16.f32 "
        "{%0,%1,%2,%3}, {%4,%5,%6,%7}, {%8,%9}, {%0,%1,%2,%3};"
        : "+f"(c[0]), "+f"(c[1]), "+f"(c[2]), "+f"(c[3])
        : "r"(a[0]), "r"(a[1]), "r"(a[2]), "r"(a[3]), "r"(b[0]), "r"(b[1]));
}
__device__ __forceinline__ void cp16(uint32_t dst, const void* src) {
    asm volatile("cp.async.cg.shared.global [%0], [%1], 16;" :: "r"(dst), "l"(src));
}
__device__ __forceinline__ float fexp2(float x) {
    float y;
    asm("ex2.approx.f32 %0, %1;" : "=f"(y) : "f"(x));
    return y;
}
__device__ __forceinline__ uint32_t pack_hi2(float x, float y, float& rx, float& ry) {
    __nv_bfloat16 hx = __float2bfloat16_rn(x);
    __nv_bfloat16 hy = __float2bfloat16_rn(y);
    rx = x - __bfloat162float(hx);
    ry = y - __bfloat162float(hy);
    return ((uint32_t)__bfloat16_as_ushort(hy) << 16) | (uint32_t)__bfloat16_as_ushort(hx);
}
__device__ __forceinline__ uint32_t pack_bf2(float x, float y) {
    return ((uint32_t)__bfloat16_as_ushort(__float2bfloat16_rn(y)) << 16)
         | (uint32_t)__bfloat16_as_ushort(__float2bfloat16_rn(x));
}

// ---------------------------------------------------------------------------
// Convert X (q, key_t, value) -> bf16 hi/lo
// ---------------------------------------------------------------------------
__global__ __launch_bounds__(256) void convx_kernel(
    const float* __restrict__ q, const float* __restrict__ kt, const float* __restrict__ v)
{
    int p = blockIdx.y;
    const float* X = (p == 0) ? q : (p == 1) ? kt : v;
    __nv_bfloat16* hi = g_Xhi + (size_t)p * BLV_;
    __nv_bfloat16* lo = g_Xlo + (size_t)p * BLV_;
    size_t i0 = ((size_t)blockIdx.x * 256 + threadIdx.x) * 8;
    float x[8];
    *(float4*)&x[0] = *(const float4*)(X + i0);
    *(float4*)&x[4] = *(const float4*)(X + i0 + 4);
    __nv_bfloat16 hb[8], lb[8];
    #pragma unroll
    for (int i = 0; i < 8; i++) {
        __nv_bfloat16 h = __float2bfloat16_rn(x[i]);
        hb[i] = h;
        lb[i] = __float2bfloat16_rn(x[i] - __bfloat162float(h));
    }
    *(uint4*)(hi + i0) = *(uint4*)hb;
    *(uint4*)(lo + i0) = *(uint4*)lb;
}

// ---------------------------------------------------------------------------
// Convert + transpose W: W[h][v][d] -> Wt[n=h*64+d][v] bf16 hi/lo
// ---------------------------------------------------------------------------
__global__ __launch_bounds__(256) void convw_kernel(
    const float* __restrict__ Wq, const float* __restrict__ Wk, const float* __restrict__ Wv)
{
    __shared__ float s[64][65];
    int v0 = blockIdx.x * 64, h = blockIdx.y, p = blockIdx.z;
    const float* W = ((p == 0) ? Wq : (p == 1) ? Wk : Wv) + (size_t)h * V_ * HD_;
    __nv_bfloat16* Whi = g_Wthi + (size_t)p * NV_;
    __nv_bfloat16* Wlo = g_Wtlo + (size_t)p * NV_;
    int t = threadIdx.x;
    int r16 = t >> 4, c4 = (t & 15) * 4;
    #pragma unroll
    for (int u = 0; u < 4; u++) {
        int row = r16 + u * 16;
        float4 a = *(const float4*)(W + (size_t)(v0 + row) * HD_ + c4);
        s[row][c4 + 0] = a.x; s[row][c4 + 1] = a.y; s[row][c4 + 2] = a.z; s[row][c4 + 3] = a.w;
    }
    __syncthreads();
    #pragma unroll
    for (int u = 0; u < 4; u++) {
        int d = r16 + u * 16;
        __nv_bfloat16 hb[4], lb[4];
        #pragma unroll
        for (int j = 0; j < 4; j++) {
            float x = s[c4 + j][d];
            __nv_bfloat16 hh = __float2bfloat16_rn(x);
            hb[j] = hh;
            lb[j] = __float2bfloat16_rn(x - __bfloat162float(hh));
        }
        size_t o = ((size_t)(h * 64 + d) << 10) + v0 + c4;
        *(uint2*)(Whi + o) = *(uint2*)hb;
        *(uint2*)(Wlo + o) = *(uint2*)lb;
    }
}

// ---------------------------------------------------------------------------
// Projection GEMM via mma.sync bf16 3-term split (R10 direct-load version).
// Writes bf16 hi/lo directly: p=0 Q*0.125*log2e, p=1 K, p=2 V*vmask.
// ---------------------------------------------------------------------------
#define SK_ 40

__global__ __launch_bounds__(256) void proj_mma_kernel(const int* __restrict__ vmask)
{
    __shared__ __nv_bfloat16 sm[4][128][SK_];

    int tid = threadIdx.x;
    int wid = tid >> 5, lane = tid & 31;
    int warp_m = wid & 3, warp_n = wid >> 2;

    int l0  = blockIdx.x * 128;
    int n0g = blockIdx.y * 128;
    int p   = blockIdx.z >> 1;
    int b   = blockIdx.z & 1;

    const __nv_bfloat16* Xhi = g_Xhi + (size_t)p * BLV_ + (size_t)b * L_ * V_;
    const __nv_bfloat16* Xlo = g_Xlo + (size_t)p * BLV_ + (size_t)b * L_ * V_;
    const __nv_bfloat16* Whi = g_Wthi + (size_t)p * NV_;
    const __nv_bfloat16* Wlo = g_Wtlo + (size_t)p * NV_;
    __nv_bfloat16* Ah = g_Ah + (size_t)p * BLV_ + (size_t)b * L_ * V_;
    __nv_bfloat16* Al = g_Al + (size_t)p * BLV_ + (size_t)b * L_ * V_;

    float acc[2][8][4] = {};

    uint32_t smb = smem_u32(&sm[0][0][0]);
    uint32_t a_row = (uint32_t)(warp_m * 32 + (lane & 15));
    uint32_t a_koff = (uint32_t)((lane >> 4) * 8);
    uint32_t b_row = (uint32_t)(warp_n * 64 + ((lane >> 4) & 1) * 8 + (lane & 7));
    uint32_t b_koff = (uint32_t)(((lane >> 3) & 1) * 8);

    for (int kc = 0; kc < V_ / 32; kc++) {
        int k0 = kc * 32;
        #pragma unroll
        for (int u = 0; u < 2; u++) {
            int idx = tid + u * 256;
            int row = idx >> 2;
            int c8  = (idx & 3) * 8;
            size_t goA = ((size_t)(l0 + row) << 10) + k0 + c8;
            size_t goB = ((size_t)(n0g + row) << 10) + k0 + c8;
            *(uint4*)&sm[0][row][c8] = *(const uint4*)(Xhi + goA);
            *(uint4*)&sm[1][row][c8] = *(const uint4*)(Xlo + goA);
            *(uint4*)&sm[2][row][c8] = *(const uint4*)(Whi + goB);
            *(uint4*)&sm[3][row][c8] = *(const uint4*)(Wlo + goB);
        }
        __syncthreads();

        #pragma unroll
        for (int ks = 0; ks < 2; ks++) {
            uint32_t ah[2][4], al[2][4];
            #pragma unroll
            for (int mt = 0; mt < 2; mt++) {
                uint32_t off = ((a_row + mt * 16) * SK_ + ks * 16 + a_koff) * 2;
                ldsm4(ah[mt], smb + 0 * 128 * SK_ * 2 + off);
                ldsm4(al[mt], smb + 1 * 128 * SK_ * 2 + off);
            }
            uint32_t bh[4][4], bl[4][4];
            #pragma unroll
            for (int nt2 = 0; nt2 < 4; nt2++) {
                uint32_t off = ((b_row + nt2 * 16) * SK_ + ks * 16 + b_koff) * 2;
                ldsm4(bh[nt2], smb + 2 * 128 * SK_ * 2 + off);
                ldsm4(bl[nt2], smb + 3 * 128 * SK_ * 2 + off);
            }
            #pragma unroll
            for (int mt = 0; mt < 2; mt++)
                #pragma unroll
                for (int nt = 0; nt < 8; nt++) {
                    const uint32_t* bfh = &bh[nt >> 1][(nt & 1) * 2];
                    const uint32_t* bfl = &bl[nt >> 1][(nt & 1) * 2];
                    mma16816(acc[mt][nt], ah[mt], bfh);
                    mma16816(acc[mt][nt], ah[mt], bfl);
                    mma16816(acc[mt][nt], al[mt], bfh);
                }
        }
        __syncthreads();
    }

    // Epilogue: scale + split hi/lo + 4B stores
    int mrow = warp_m * 32 + (lane >> 2);
    int ncol = warp_n * 64 + 2 * (lane & 3);
    #pragma unroll
    for (int mt = 0; mt < 2; mt++) {
        int m0r = l0 + mrow + mt * 16;
        float s0 = 1.f, s1 = 1.f;
        if (p == 0) { s0 = 0.125f * LOG2E_; s1 = s0; }
        else if (p == 2) {
            s0 = (float)vmask[b * L_ + m0r];
            s1 = (float)vmask[b * L_ + m0r + 8];
        }
        #pragma unroll
        for (int nt = 0; nt < 8; nt++) {
            int n = ncol + nt * 8;
            float r0, r1;
            uint32_t hi0 = pack_hi2(acc[mt][nt][0] * s0, acc[mt][nt][1] * s0, r0, r1);
            uint32_t lo0 = pack_bf2(r0, r1);
            *(uint32_t*)(Ah + (size_t)m0r * V_ + n0g + n) = hi0;
            *(uint32_t*)(Al + (size_t)m0r * V_ + n0g + n) = lo0;
            uint32_t hi1 = pack_hi2(acc[mt][nt][2] * s1, acc[mt][nt][3] * s1, r0, r1);
            uint32_t lo1 = pack_bf2(r0, r1);
            *(uint32_t*)(Ah + (size_t)(m0r + 8) * V_ + n0g + n) = hi1;
            *(uint32_t*)(Al + (size_t)(m0r + 8) * V_ + n0g + n) = lo1;
        }
    }
}

// ---------------------------------------------------------------------------
// Tensor-core flash attention; scores in log2 domain (Q pre-scaled by
// 0.125*log2e), softmax via ex2.approx. Full-row denominator; post-softmax
// causal mask on numerator; vmask folded into V; qmask in epilogue.
// cp.async double-buffered K/V tiles.
// ---------------------------------------------------------------------------
#define SKA_ 72
#define QH_OFF 0
#define QL_OFF (128 * SKA_)
#define BUF0_  (2 * 128 * SKA_)
#define KHO_   0
#define KLO_   (64 * SKA_)
#define VHO_   (2 * 64 * SKA_)
#define VLO_   (3 * 64 * SKA_)
#define BUFS_  (4 * 64 * SKA_)
#define ATT_SMEM ((BUF0_ + 2 * BUFS_) * 2)   // 110592 bytes

__global__ __launch_bounds__(256, 2) void attn_mma_kernel(const int* __restrict__ qmask)
{
    extern __shared__ __nv_bfloat16 smb16[];
    uint32_t smb = smem_u32(smb16);

    int b  = blockIdx.z, h = blockIdx.y;
    int l0 = blockIdx.x * 128;
    int tid = threadIdx.x;
    int w = tid >> 5, lane = tid & 31;

    const __nv_bfloat16* Qh = g_Ah + ((size_t)b * L_) * V_ + h * HD_;
    const __nv_bfloat16* Ql = g_Al + ((size_t)b * L_) * V_ + h * HD_;
    const __nv_bfloat16* Kh = g_Ah + (size_t)1 * BLV_ + ((size_t)b * L_) * V_ + h * HD_;
    const __nv_bfloat16* Kl = g_Al + (size_t)1 * BLV_ + ((size_t)b * L_) * V_ + h * HD_;
    const __nv_bfloat16* Vh = g_Ah + (size_t)2 * BLV_ + ((size_t)b * L_) * V_ + h * HD_;
    const __nv_bfloat16* Vl = g_Al + (size_t)2 * BLV_ + ((size_t)b * L_) * V_ + h * HD_;

    const int kt_pv = 2 * blockIdx.x + 1;

    // ---- Load Q tile (128x64 hi/lo) ----
    #pragma unroll
    for (int u = 0; u < 4; u++) {
        int idx = tid + u * 256;
        int row = idx >> 3, ch = (idx & 7) * 8;
        *(uint4*)(smb16 + QH_OFF + row * SKA_ + ch) = *(const uint4*)(Qh + (size_t)(l0 + row) * V_ + ch);
        *(uint4*)(smb16 + QL_OFF + row * SKA_ + ch) = *(const uint4*)(Ql + (size_t)(l0 + row) * V_ + ch);
    }

    int pf_row0 = tid >> 3, pf_ch = (tid & 7) * 8;

    // ---- Prefetch tile 0 ----
    {
        uint32_t base = smb + BUF0_ * 2;
        #pragma unroll
        for (int u = 0; u < 2; u++) {
            int row = pf_row0 + u * 32;
            uint32_t so = (uint32_t)(row * SKA_ + pf_ch) * 2;
            size_t go = (size_t)row * V_ + pf_ch;
            cp16(base + KHO_ * 2 + so, Kh + go);
            cp16(base + KLO_ * 2 + so, Kl + go);
            cp16(base + VHO_ * 2 + so, Vh + go);
            cp16(base + VLO_ * 2 + so, Vl + go);
        }
        asm volatile("cp.async.commit_group;" ::: "memory");
    }

    uint32_t qa_row  = (uint32_t)(w * 16 + (lane & 15));
    uint32_t qa_koff = (uint32_t)((lane >> 4) * 8);
    uint32_t kb_row  = (uint32_t)(((lane >> 4) & 1) * 8 + (lane & 7));
    uint32_t kb_koff = (uint32_t)(((lane >> 3) & 1) * 8);
    uint32_t vb_row  = (uint32_t)(((lane >> 3) & 1) * 8 + (lane & 7));
    uint32_t vb_coff = (uint32_t)((lane >> 4) * 8);

    float o[8][4] = {};
    float rmax0 = -1e30f, rmax1 = -1e30f;
    float rden0 = 0.f, rden1 = 0.f;

    for (int kt = 0; kt < L_ / 64; kt++) {
        int m0 = kt * 64;
        bool need_pv = (kt <= kt_pv);

        if (kt < L_ / 64 - 1) {
            int m1 = m0 + 64;
            bool pv1 = (kt + 1 <= kt_pv);
            uint32_t base = smb + (BUF0_ + ((kt + 1) & 1) * BUFS_) * 2;
            #pragma unroll
            for (int u = 0; u < 2; u++) {
                int row = pf_row0 + u * 32;
                uint32_t so = (uint32_t)(row * SKA_ + pf_ch) * 2;
                size_t go = (size_t)(m1 + row) * V_ + pf_ch;
                cp16(base + KHO_ * 2 + so, Kh + go);
                cp16(base + KLO_ * 2 + so, Kl + go);
                if (pv1) {
                    cp16(base + VHO_ * 2 + so, Vh + go);
                    cp16(base + VLO_ * 2 + so, Vl + go);
                }
            }
            asm volatile("cp.async.commit_group;" ::: "memory");
            asm volatile("cp.async.wait_group 1;" ::: "memory");
        } else {
            asm volatile("cp.async.wait_group 0;" ::: "memory");
        }
        __syncthreads();

        uint32_t kbase = smb + (BUF0_ + (kt & 1) * BUFS_) * 2;

        // ---- S' = (Q*0.125*log2e) K^T, 3-term split ----
        float s[8][4] = {};
        #pragma unroll
        for (int ks = 0; ks < 4; ks++) {
            uint32_t ah[4], al[4];
            uint32_t qoff = (qa_row * SKA_ + ks * 16 + qa_koff) * 2;
            ldsm4(ah, smb + QH_OFF * 2 + qoff);
            ldsm4(al, smb + QL_OFF * 2 + qoff);
            #pragma unroll
            for (int nt = 0; nt < 4; nt++) {
                uint32_t bh[4], bl[4];
                uint32_t koff = ((nt * 16 + kb_row) * SKA_ + ks * 16 + kb_koff) * 2;
                ldsm4(bh, kbase + KHO_ * 2 + koff);
                ldsm4(bl, kbase + KLO_ * 2 + koff);
                #pragma unroll
                for (int half = 0; half < 2; half++) {
                    float* sj = s[2 * nt + half];
                    mma16816(sj, ah, &bh[half * 2]);
                    mma16816(sj, ah, &bl[half * 2]);
                    mma16816(sj, al, &bh[half * 2]);
                }
            }
        }

        // ---- Online softmax in log2 domain (2 rows per thread) ----
        float ml0 = -1e30f, ml1 = -1e30f;
        #pragma unroll
        for (int j = 0; j < 8; j++) {
            ml0 = fmaxf(ml0, fmaxf(s[j][0], s[j][1]));
            ml1 = fmaxf(ml1, fmaxf(s[j][2], s[j][3]));
        }
        ml0 = fmaxf(ml0, __shfl_xor_sync(0xffffffffu, ml0, 1));
        ml0 = fmaxf(ml0, __shfl_xor_sync(0xffffffffu, ml0, 2));
        ml1 = fmaxf(ml1, __shfl_xor_sync(0xffffffffu, ml1, 1));
        ml1 = fmaxf(ml1, __shfl_xor_sync(0xffffffffu, ml1, 2));

        float mn0 = fmaxf(rmax0, ml0), mn1 = fmaxf(rmax1, ml1);
        float sc0 = fexp2(rmax0 - mn0), sc1 = fexp2(rmax1 - mn1);
        rmax0 = mn0; rmax1 = mn1;

        float rs0 = 0.f, rs1 = 0.f;
        #pragma unroll
        for (int j = 0; j < 8; j++) {
            s[j][0] = fexp2(s[j][0] - mn0);
            s[j][1] = fexp2(s[j][1] - mn0);
            s[j][2] = fexp2(s[j][2] - mn1);
            s[j][3] = fexp2(s[j][3] - mn1);
            rs0 += s[j][0] + s[j][1];
            rs1 += s[j][2] + s[j][3];
        }
        rs0 += __shfl_xor_sync(0xffffffffu, rs0, 1);
        rs0 += __shfl_xor_sync(0xffffffffu, rs0, 2);
        rs1 += __shfl_xor_sync(0xffffffffu, rs1, 1);
        rs1 += __shfl_xor_sync(0xffffffffu, rs1, 2);
        rden0 = rden0 * sc0 + rs0;
        rden1 = rden1 * sc1 + rs1;
        #pragma unroll
        for (int j = 0; j < 8; j++) {
            o[j][0] *= sc0; o[j][1] *= sc0;
            o[j][2] *= sc1; o[j][3] *= sc1;
        }

        if (need_pv) {
            int lg0 = l0 + w * 16 + (lane >> 2);
            int lg1 = lg0 + 8;
            #pragma unroll
            for (int j = 0; j < 8; j++) {
                int mg = m0 + (j >> 1) * 16 + (j & 1) * 8 + (lane & 3) * 2;
                if (mg > lg0)     s[j][0] = 0.f;
                if (mg + 1 > lg0) s[j][1] = 0.f;
                if (mg > lg1)     s[j][2] = 0.f;
                if (mg + 1 > lg1) s[j][3] = 0.f;
            }
            #pragma unroll
            for (int kc = 0; kc < 4; kc++) {
                int j0 = 2 * kc, j1 = 2 * kc + 1;
                uint32_t ap[4], alo[4];
                float r0, r1;
                ap[0] = pack_hi2(s[j0][0], s[j0][1], r0, r1); alo[0] = pack_bf2(r0, r1);
                ap[1] = pack_hi2(s[j0][2], s[j0][3], r0, r1); alo[1] = pack_bf2(r0, r1);
                ap[2] = pack_hi2(s[j1][0], s[j1][1], r0, r1); alo[2] = pack_bf2(r0, r1);
                ap[3] = pack_hi2(s[j1][2], s[j1][3], r0, r1); alo[3] = pack_bf2(r0, r1);
                #pragma unroll
                for (int nt = 0; nt < 4; nt++) {
                    uint32_t bvh[4], bvl[4];
                    uint32_t voff = ((kc * 16 + vb_row) * SKA_ + nt * 16 + vb_coff) * 2;
                    ldsm4t(bvh, kbase + VHO_ * 2 + voff);
                    ldsm4t(bvl, kbase + VLO_ * 2 + voff);
                    #pragma unroll
                    for (int half = 0; half < 2; half++) {
                        float* oj = o[2 * nt + half];
                        mma16816(oj, ap, &bvh[half * 2]);
                        mma16816(oj, ap, &bvl[half * 2]);
                        mma16816(oj, alo, &bvh[half * 2]);
                    }
                }
            }
        }
        __syncthreads();
    }

    // ---- Epilogue: qm / den, write heads ----
    int lg0 = l0 + w * 16 + (lane >> 2);
    int lg1 = lg0 + 8;
    float inv0 = (float)qmask[b * L_ + lg0] / rden0;
    float inv1 = (float)qmask[b * L_ + lg1] / rden1;
    float* Og = g_Hd + ((size_t)b * L_) * V_ + h * HD_;
    #pragma unroll
    for (int j = 0; j < 8; j++) {
        int d = (j >> 1) * 16 + (j & 1) * 8 + (lane & 3) * 2;
        float2 a0 = {o[j][0] * inv0, o[j][1] * inv0};
        float2 a1 = {o[j][2] * inv1, o[j][3] * inv1};
        *(float2*)(Og + (size_t)lg0 * V_ + d) = a0;
        *(float2*)(Og + (size_t)lg1 * V_ + d) = a1;
    }
}

// ---------------------------------------------------------------------------
// Residual + LayerNorm
// ---------------------------------------------------------------------------
__global__ __launch_bounds__(256) void ln_kernel(
    const float* __restrict__ query, const float* __restrict__ gamma,
    const float* __restrict__ beta, float* __restrict__ out)
{
    __shared__ float rsum[8], rsum2[8], stats[2];
    int row = blockIdx.x, tid = threadIdx.x;
    const float* hrow = g_Hd + (size_t)row * V_;
    const float* qrow = query + (size_t)row * V_;

    float4 h4 = *(const float4*)(hrow + tid * 4);
    float4 q4 = *(const float4*)(qrow + tid * 4);
    float y[4] = {h4.x + q4.x, h4.y + q4.y, h4.z + q4.z, h4.w + q4.w};
    float s  = y[0] + y[1] + y[2] + y[3];
    float s2 = y[0]*y[0] + y[1]*y[1] + y[2]*y[2] + y[3]*y[3];
    #pragma unroll
    for (int off = 16; off; off >>= 1) {
        s  += __shfl_xor_sync(0xffffffffu, s,  off);
        s2 += __shfl_xor_sync(0xffffffffu, s2, off);
    }
    if ((tid & 31) == 0) { rsum[tid >> 5] = s; rsum2[tid >> 5] = s2; }
    __syncthreads();
    if (tid == 0) {
        float ts = 0.f, ts2 = 0.f;
        #pragma unroll
        for (int i = 0; i < 8; i++) { ts += rsum[i]; ts2 += rsum2[i]; }
        float mu  = ts * (1.f / V_);
        float var = ts2 * (1.f / V_) - mu * mu;
        stats[0] = mu;
        stats[1] = rsqrtf(var + EPS_);
    }
    __syncthreads();
    float mu = stats[0], inv = stats[1];
    float4 g4 = *(const float4*)(gamma + tid * 4);
    float4 b4 = *(const float4*)(beta  + tid * 4);
    float4 o;
    o.x = g4.x * (y[0] - mu) * inv + b4.x;
    o.y = g4.y * (y[1] - mu) * inv + b4.y;
    o.z = g4.z * (y[2] - mu) * inv + b4.z;
    o.w = g4.w * (y[3] - mu) * inv + b4.w;
    *(float4*)(out + (size_t)row * V_ + tid * 4) = o;
}

// ---------------------------------------------------------------------------
extern "C" void kernel_launch(void* const* d_in, const int* in_sizes, int n_in,
                              void* d_out, int out_size)
{
    const float* query = (const float*)d_in[0];
    const float* key_t = (const float*)d_in[1];
    const float* value = (const float*)d_in[2];
    const float* Wq    = (const float*)d_in[3];
    const float* Wk    = (const float*)d_in[4];
    const float* Wv    = (const float*)d_in[5];
    const float* gamma = (const float*)d_in[6];
    const float* beta  = (const float*)d_in[7];
    const int*   qmask = (const int*)d_in[8];
    const int*   vmask = (const int*)d_in[9];
    float* out = (float*)d_out;

    convx_kernel<<<dim3(BLV_ / 2048, 3), 256>>>(query, key_t, value);
    convw_kernel<<<dim3(V_ / 64, H_, 3), 256>>>(Wq, Wk, Wv);

    proj_mma_kernel<<<dim3(L_ / 128, V_ / 128, 3 * B_), 256>>>(vmask);

    cudaFuncSetAttribute(attn_mma_kernel, cudaFuncAttributeMaxDynamicSharedMemorySize, ATT_SMEM);
    attn_mma_kernel<<<dim3(L_ / 128, H_, B_), 256, ATT_SMEM>>>(qmask);

    ln_kernel<<<B_ * L_, 256>>>(query, gamma, beta, out);
}